// round 4
// baseline (speedup 1.0000x reference)
#include <cuda_runtime.h>
#include <cuda_bf16.h>
#include <cstdint>

// ---------------- arch-feature gate ----------------
// tcgen05 (incl. tcgen05.ld/wait/dealloc) needs the arch-SPECIFIC target
// (sm_103a). In a plain compute_103/sm_103 pass these macros are undefined and
// we compile the FFMA fallback body instead, so every gencode pass is valid.
#if defined(__CUDA_ARCH_FEAT_SM103_ALL) || defined(__CUDA_ARCH_FEAT_SM100_ALL) || \
    defined(__CUDA_ARCH_FEAT_SM101_ALL) ||                                        \
    (defined(__CUDA_ARCH_SPECIFIC__) && (__CUDA_ARCH_SPECIFIC__ >= 1000))
#define HAS_TCGEN05 1
#else
#define HAS_TCGEN05 0
#endif

// ---------------- tiling ----------------
// out[f, hw] computed as D[hw, f] = sum_c X[c,hw] * W[f,c]   (A = X^T, B = W)
// CTA tile: HW=128 (one M-atom), F=256 (2 MMAs of N=128), K=512 in 8 chunks of 64.
// 3 MMA passes per chunk: Ahi*Bhi + Ahi*Blo + Alo*Bhi (bf16 split of fp32).
#define NCHUNK 8
#define KC 64
#define NSTAGE 2

// ---------------- smem layout ----------------
// 0     : tmem base ptr
// 16..47: mbarriers full[s]@16+16s, empty[s]@24+16s
// 64    : bias tile (256 floats)
// 4096 + s*98304 : stage s { Ahi 16K | Alo 16K | Bhi 32K | Blo 32K }
//   A: 128 hw-rows x 128B (64 bf16 c), SW128 K-major
//   B: 256 f-rows  x 128B (64 bf16 c), SW128 K-major
#define STAGE0    4096
#define STAGE_SZ  98304
#define A_HI      0
#define A_LO      16384
#define B_HI      32768
#define B_LO      65536
#define BIAS_OFF  64
#define SMEM_TOTAL (STAGE0 + NSTAGE * STAGE_SZ)   // 200704
#define MBAR_FULL(s)  (16u + 16u * (s))
#define MBAR_EMPTY(s) (24u + 16u * (s))

// idesc (kind::f16): dtype=F32(bit4), atype=BF16(bit7), btype=BF16(bit10),
// N=128 -> 16<<17, M=128 -> 8<<24   (same field pattern as the verified examples)
static constexpr unsigned IDESC =
    (1u << 4) | (1u << 7) | (1u << 10) | (16u << 17) | (8u << 24);

__device__ __forceinline__ uint32_t smem_u32(const void* p) {
    uint32_t a;
    asm("{ .reg .u64 t; cvta.to.shared.u64 t, %1; cvt.u32.u64 %0, t; }" : "=r"(a) : "l"(p));
    return a;
}

#if HAS_TCGEN05
__device__ __forceinline__ void mbar_init(uint32_t a, uint32_t cnt) {
    asm volatile("mbarrier.init.shared.b64 [%0], %1;" :: "r"(a), "r"(cnt) : "memory");
}
__device__ __forceinline__ void mbar_arrive(uint32_t a) {
    asm volatile("mbarrier.arrive.shared.b64 _, [%0];" :: "r"(a) : "memory");
}
__device__ __forceinline__ void mbar_wait(uint32_t a, uint32_t parity) {
    asm volatile(
        "{\n\t.reg .pred P;\n\t"
        "WL%=:\n\t"
        "mbarrier.try_wait.parity.acquire.cta.shared::cta.b64 P, [%0], %1, 0x989680;\n\t"
        "@!P bra WL%=;\n\t}"
        :: "r"(a), "r"(parity) : "memory");
}
// SW128 K-major descriptor: layout=2, version=1, SBO=64 (1024B/8-row group), LBO=1
__device__ __forceinline__ uint64_t sw128_desc(uint32_t addr) {
    return (2ull << 61) | (1ull << 46) | (64ull << 32) | (1ull << 16) |
           ((uint64_t)(addr >> 4) & 0x3FFFull);
}
__device__ __forceinline__ void mma_ss(uint32_t d, uint64_t ad, uint64_t bd, uint32_t en) {
    asm volatile(
        "{\n\t.reg .pred p;\n\tsetp.ne.u32 p, %4, 0;\n\t"
        "tcgen05.mma.cta_group::1.kind::f16 [%0], %1, %2, %3, {%5,%5,%5,%5}, p;\n\t}"
        :: "r"(d), "l"(ad), "l"(bd), "r"(IDESC), "r"(en), "r"(0u) : "memory");
}
__device__ __forceinline__ void mma_commit(uint32_t mbar) {
    asm volatile(
        "tcgen05.commit.cta_group::1.mbarrier::arrive::one.shared::cluster.b64 [%0];"
        :: "r"(mbar) : "memory");
}
__device__ __forceinline__ void ldtm_x32(uint32_t* r, uint32_t a) {
    asm volatile(
        "tcgen05.ld.sync.aligned.32x32b.x32.b32 "
        "{%0, %1, %2, %3, %4, %5, %6, %7, "
        " %8, %9, %10, %11, %12, %13, %14, %15, "
        " %16, %17, %18, %19, %20, %21, %22, %23, "
        " %24, %25, %26, %27, %28, %29, %30, %31}, [%32];"
        : "=r"(r[0]),  "=r"(r[1]),  "=r"(r[2]),  "=r"(r[3]),
          "=r"(r[4]),  "=r"(r[5]),  "=r"(r[6]),  "=r"(r[7]),
          "=r"(r[8]),  "=r"(r[9]),  "=r"(r[10]), "=r"(r[11]),
          "=r"(r[12]), "=r"(r[13]), "=r"(r[14]), "=r"(r[15]),
          "=r"(r[16]), "=r"(r[17]), "=r"(r[18]), "=r"(r[19]),
          "=r"(r[20]), "=r"(r[21]), "=r"(r[22]), "=r"(r[23]),
          "=r"(r[24]), "=r"(r[25]), "=r"(r[26]), "=r"(r[27]),
          "=r"(r[28]), "=r"(r[29]), "=r"(r[30]), "=r"(r[31])
        : "r"(a));
}
#endif  // HAS_TCGEN05

__device__ __forceinline__ uint32_t pack_lo_bf16x2(float x0, float x1) {
    __nv_bfloat162 p = __floats2bfloat162_rn(x0, x1);
    return *reinterpret_cast<uint32_t*>(&p);
}

// grid: 1024 CTAs.  f0 = (bid&1)*256, hw0 = (bid>>1)*128.
__global__ void __launch_bounds__(256, 1)
spconv_kernel(const float* __restrict__ X, const float* __restrict__ W,
              const float* __restrict__ bias, float* __restrict__ out)
{
    extern __shared__ char smem[];
    const int tid = threadIdx.x;
    const int f0  = (blockIdx.x & 1) * 256;
    const int hw0 = (blockIdx.x >> 1) * 128;

#if HAS_TCGEN05
    // =================== tcgen05 path (sm_103a) ===================
    const uint32_t sb = smem_u32(smem);
    const int wid = tid >> 5;
    const int lane = tid & 31;

    if (wid == 0) {
        asm volatile("tcgen05.alloc.cta_group::1.sync.aligned.shared::cta.b32 [%0], %1;"
                     :: "r"(sb), "r"(256u) : "memory");
        asm volatile("tcgen05.relinquish_alloc_permit.cta_group::1.sync.aligned;" ::: "memory");
    }
    if (tid == 0) {
        #pragma unroll
        for (int s = 0; s < NSTAGE; s++) {
            mbar_init(sb + MBAR_FULL(s), 256);
            mbar_init(sb + MBAR_EMPTY(s), 1);
        }
    }
    reinterpret_cast<float*>(smem + BIAS_OFF)[tid] = bias[f0 + tid];
    __syncthreads();
    uint32_t tmem;
    asm volatile("ld.shared.b32 %0, [%1];" : "=r"(tmem) : "r"(sb));

    int pst = 0, pph = 1;   // producer cursor (first empty-wait passes)
    int cst = 0, cph = 0;   // MMA-issue cursor

    for (int ch = 0; ch < NCHUNK; ch++) {
        mbar_wait(sb + MBAR_EMPTY(pst), (uint32_t)pph);
        char* stg = smem + STAGE0 + pst * STAGE_SZ;
        const int c0 = ch * KC;

        // ---- B = W tile: 256 f-rows x 64 c, fp32 -> bf16 hi/lo, SW128 K-major ----
        #pragma unroll
        for (int i = 0; i < 16; i++) {
            int l = tid + 256 * i;               // 4096 float4s
            int row = l >> 4;                    // f row 0..255
            int cl4 = l & 15;                    // float4 along c
            float4 v = *reinterpret_cast<const float4*>(
                W + (size_t)(f0 + row) * 512 + c0 + cl4 * 4);
            uint32_t x0 = __float_as_uint(v.x), x1 = __float_as_uint(v.y);
            uint32_t x2 = __float_as_uint(v.z), x3 = __float_as_uint(v.w);
            uint32_t h01 = __byte_perm(x0, x1, 0x7632);
            uint32_t h23 = __byte_perm(x2, x3, 0x7632);
            uint32_t l01 = pack_lo_bf16x2(v.x - __uint_as_float(x0 & 0xFFFF0000u),
                                          v.y - __uint_as_float(x1 & 0xFFFF0000u));
            uint32_t l23 = pack_lo_bf16x2(v.z - __uint_as_float(x2 & 0xFFFF0000u),
                                          v.w - __uint_as_float(x3 & 0xFFFF0000u));
            uint32_t off = (uint32_t)(row * 128 + cl4 * 8);
            off ^= (off >> 3) & 0x70;            // SW128 swizzle
            *reinterpret_cast<uint2*>(stg + B_HI + off) = make_uint2(h01, h23);
            *reinterpret_cast<uint2*>(stg + B_LO + off) = make_uint2(l01, l23);
        }

        // ---- A = X^T tile: 64 c x 128 hw -> [128 hw-rows x 64 c], SW128 ----
        // lane = c-pair (conflict-free STS: lanes sweep a 128B row)
        #pragma unroll
        for (int i = 0; i < 4; i++) {
            int q = wid + 8 * i;                 // hw float4-group 0..31
            const float* xa = X + (size_t)(c0 + 2 * lane) * 65536 + hw0 + q * 4;
            float4 va = *reinterpret_cast<const float4*>(xa);
            float4 vb = *reinterpret_cast<const float4*>(xa + 65536);
            const float* pa = reinterpret_cast<const float*>(&va);
            const float* pb = reinterpret_cast<const float*>(&vb);
            #pragma unroll
            for (int e = 0; e < 4; e++) {
                float fa = pa[e], fb = pb[e];
                uint32_t ua = __float_as_uint(fa), ub = __float_as_uint(fb);
                uint32_t hi = __byte_perm(ua, ub, 0x7632);
                uint32_t lo = pack_lo_bf16x2(fa - __uint_as_float(ua & 0xFFFF0000u),
                                             fb - __uint_as_float(ub & 0xFFFF0000u));
                uint32_t off = (uint32_t)((q * 4 + e) * 128 + lane * 4);
                off ^= (off >> 3) & 0x70;
                *reinterpret_cast<uint32_t*>(stg + A_HI + off) = hi;
                *reinterpret_cast<uint32_t*>(stg + A_LO + off) = lo;
            }
        }

        asm volatile("fence.proxy.async.shared::cta;" ::: "memory");
        mbar_arrive(sb + MBAR_FULL(pst));
        if (++pst == NSTAGE) { pst = 0; pph ^= 1; }

        // ---- MMA issue (one thread) ----
        if (tid == 0) {
            mbar_wait(sb + MBAR_FULL(cst), (uint32_t)cph);
            asm volatile("tcgen05.fence::after_thread_sync;" ::: "memory");
            uint32_t base = sb + STAGE0 + cst * STAGE_SZ;
            #pragma unroll
            for (int k = 0; k < 4; k++) {        // K=16 steps within 64-c chunk
                uint64_t ah = sw128_desc(base + A_HI) + k * 2;
                uint64_t al = sw128_desc(base + A_LO) + k * 2;
                #pragma unroll
                for (int nh = 0; nh < 2; nh++) { // f halves (N=128 each)
                    uint64_t bh = sw128_desc(base + B_HI) + nh * 1024 + k * 2;
                    uint64_t bl = sw128_desc(base + B_LO) + nh * 1024 + k * 2;
                    uint32_t d = tmem + nh * 128;
                    mma_ss(d, ah, bh, (ch == 0 && k == 0) ? 0u : 1u);
                    mma_ss(d, ah, bl, 1u);
                    mma_ss(d, al, bh, 1u);
                }
            }
            mma_commit(sb + MBAR_EMPTY(cst));
            if (++cst == NSTAGE) { cst = 0; cph ^= 1; }
        }
    }

    // ---- epilogue: wait final commit (in-order pipe => all MMAs done) ----
    {
        const int ls = (NCHUNK - 1) % NSTAGE;
        const uint32_t lp = (uint32_t)(((NCHUNK - 1) / NSTAGE) & 1);
        mbar_wait(sb + MBAR_EMPTY(ls), lp);
    }
    asm volatile("tcgen05.fence::after_thread_sync;" ::: "memory");

    const float* bias_s = reinterpret_cast<const float*>(smem + BIAS_OFF);
    const int sub  = wid & 3;                    // TMEM subpartition (fixed per warp)
    const int half = wid >> 2;                   // f half
    const int hw   = hw0 + sub * 32 + lane;
    #pragma unroll
    for (int cb = 0; cb < 4; cb++) {
        uint32_t col = (uint32_t)(half * 128 + cb * 32);
        uint32_t r[32];
        ldtm_x32(r, tmem + col);
        asm volatile("tcgen05.wait::ld.sync.aligned;" ::: "memory");
        float* op = out + (size_t)(f0 + col) * 65536 + hw;
        #pragma unroll
        for (int j = 0; j < 32; j++) {
            float v = __uint_as_float(r[j]) + bias_s[col + j];
            op[(size_t)j * 65536] = fmaxf(v, 0.0f);
        }
    }

    __syncthreads();
    if (wid == 0) {
        asm volatile("tcgen05.dealloc.cta_group::1.sync.aligned.b32 %0, %1;"
                     :: "r"(tmem), "r"(256u));
    }

#else
    // =================== FFMA fallback (plain sm_103 pass) ===================
    float* Xs = reinterpret_cast<float*>(smem + STAGE0);           // [32][128]
    float* Ws = reinterpret_cast<float*>(smem + STAGE0 + 16384);   // [256][32]
    const int tx = tid & 15, ty = tid >> 4;
    const int hw_l = tx * 8, f_l = ty * 16;

    float acc[16][8];
    #pragma unroll
    for (int i = 0; i < 16; i++)
        #pragma unroll
        for (int j = 0; j < 8; j++) acc[i][j] = 0.0f;

    for (int ch = 0; ch < 16; ch++) {
        const int c0 = ch * 32;
        #pragma unroll
        for (int i = 0; i < 4; i++) {            // X chunk 32x128
            int l = tid + 256 * i, row = l >> 5, c4 = l & 31;
            *reinterpret_cast<float4*>(&Xs[row * 128 + c4 * 4]) =
                *reinterpret_cast<const float4*>(
                    &X[(size_t)(c0 + row) * 65536 + hw0 + c4 * 4]);
        }
        #pragma unroll
        for (int i = 0; i < 8; i++) {            // W chunk 256x32
            int l = tid + 256 * i, row = l >> 3, c4 = l & 7;
            *reinterpret_cast<float4*>(&Ws[row * 32 + c4 * 4]) =
                *reinterpret_cast<const float4*>(
                    &W[(size_t)(f0 + row) * 512 + c0 + c4 * 4]);
        }
        __syncthreads();
        #pragma unroll 4
        for (int c = 0; c < 32; c++) {
            float xv[8];
            *reinterpret_cast<float4*>(xv)     = *reinterpret_cast<float4*>(&Xs[c * 128 + hw_l]);
            *reinterpret_cast<float4*>(xv + 4) = *reinterpret_cast<float4*>(&Xs[c * 128 + hw_l + 4]);
            #pragma unroll
            for (int i = 0; i < 16; i++) {
                float wv = Ws[(f_l + i) * 32 + c];
                #pragma unroll
                for (int j = 0; j < 8; j++) acc[i][j] += wv * xv[j];
            }
        }
        __syncthreads();
    }
    #pragma unroll
    for (int i = 0; i < 16; i++) {
        float b = bias[f0 + f_l + i];
        float4 o0 = make_float4(fmaxf(acc[i][0] + b, 0.f), fmaxf(acc[i][1] + b, 0.f),
                                fmaxf(acc[i][2] + b, 0.f), fmaxf(acc[i][3] + b, 0.f));
        float4 o1 = make_float4(fmaxf(acc[i][4] + b, 0.f), fmaxf(acc[i][5] + b, 0.f),
                                fmaxf(acc[i][6] + b, 0.f), fmaxf(acc[i][7] + b, 0.f));
        float* op = out + (size_t)(f0 + f_l + i) * 65536 + hw0 + hw_l;
        *reinterpret_cast<float4*>(op)     = o0;
        *reinterpret_cast<float4*>(op + 4) = o1;
    }
#endif
}

extern "C" void kernel_launch(void* const* d_in, const int* in_sizes, int n_in,
                              void* d_out, int out_size) {
    const float* X = (const float*)d_in[0];      // [1,512,256,256]
    const float* W = (const float*)d_in[1];      // [512,512] (already masked)
    // bias is the size-512 input (robust to mask dtype/position quirks)
    const float* bias = (const float*)d_in[n_in - 1];
    for (int i = 1; i < n_in; i++)
        if (in_sizes[i] == 512) { bias = (const float*)d_in[i]; break; }
    float* out = (float*)d_out;

    cudaFuncSetAttribute(spconv_kernel, cudaFuncAttributeMaxDynamicSharedMemorySize,
                         SMEM_TOTAL);
    spconv_kernel<<<1024, 256, SMEM_TOTAL>>>(X, W, bias, out);
}

// round 5
// speedup vs baseline: 1.5670x; 1.5670x over previous
#include <cuda_runtime.h>
#include <cuda_bf16.h>
#include <cstdint>

// ---------------- arch-feature gate ----------------
#if defined(__CUDA_ARCH_FEAT_SM103_ALL) || defined(__CUDA_ARCH_FEAT_SM100_ALL) || \
    defined(__CUDA_ARCH_FEAT_SM101_ALL) ||                                        \
    (defined(__CUDA_ARCH_SPECIFIC__) && (__CUDA_ARCH_SPECIFIC__ >= 1000))
#define HAS_TCGEN05 1
#else
#define HAS_TCGEN05 0
#endif

// ---------------- problem/tiling ----------------
// out[f, hw] = relu( sum_c W[f,c] * X[c,hw] + b[f] ),  F=C=512, HW=65536.
// D[hw=128, f=256] per CTA, K=512 in 16 chunks of 32, 3-pass bf16 split.
#define NCHUNK 16
#define NSTAGE 2

// Prepacked global operand tiles (written by prepass kernels):
//   g_XP[ch][hw][128B row]  row = [hi bf16 c(32ch..+31) | lo bf16], pre-SW128-swizzled
//   g_WP[ch][f ][128B row]  same structure
__device__ __align__(128) unsigned char g_XP[16ull * 65536ull * 128ull]; // 134 MB
__device__ __align__(128) unsigned char g_WP[16ull * 512ull * 128ull];   // 1 MB

// ---------------- smem layout (main kernel) ----------------
// 0: tmem ptr | 16+16s: full[s] | 24+16s: empty[s] | 48: done | 64: bias(1KB)
// 4096 + s*49152 : stage s { A 16KB | B 32KB }
#define STAGE0   4096
#define STAGE_SZ 49152
#define A_OFF    0
#define B_OFF    16384
#define BIAS_OFF 64
#define SMEM_TOTAL (STAGE0 + NSTAGE * STAGE_SZ)   // 102400
#define MBAR_FULL(s)  (16u + 16u * (s))
#define MBAR_EMPTY(s) (24u + 16u * (s))
#define MBAR_DONE     48u

// idesc kind::f16: dtype=F32(b4), atype=BF16(b7), btype=BF16(b10), N=256, M=128
static constexpr unsigned IDESC =
    (1u << 4) | (1u << 7) | (1u << 10) | (32u << 17) | (8u << 24);

__device__ __forceinline__ uint32_t smem_u32(const void* p) {
    uint32_t a;
    asm("{ .reg .u64 t; cvta.to.shared.u64 t, %1; cvt.u32.u64 %0, t; }" : "=r"(a) : "l"(p));
    return a;
}
__device__ __forceinline__ uint32_t pack_lo_bf16x2(float x0, float x1) {
    __nv_bfloat162 p = __floats2bfloat162_rn(x0, x1);
    return *reinterpret_cast<uint32_t*>(&p);
}

#if HAS_TCGEN05
__device__ __forceinline__ void mbar_init(uint32_t a, uint32_t cnt) {
    asm volatile("mbarrier.init.shared.b64 [%0], %1;" :: "r"(a), "r"(cnt) : "memory");
}
__device__ __forceinline__ void mbar_wait(uint32_t a, uint32_t parity) {
    asm volatile(
        "{\n\t.reg .pred P;\n\t"
        "WL%=:\n\t"
        "mbarrier.try_wait.parity.acquire.cta.shared::cta.b64 P, [%0], %1, 0x989680;\n\t"
        "@!P bra WL%=;\n\t}"
        :: "r"(a), "r"(parity) : "memory");
}
__device__ __forceinline__ void expect_tx(uint32_t a, uint32_t bytes) {
    asm volatile("mbarrier.arrive.expect_tx.shared.b64 _, [%0], %1;"
                 :: "r"(a), "r"(bytes) : "memory");
}
__device__ __forceinline__ void bulk_g2s(uint32_t dst, uint64_t gsrc,
                                         uint32_t bytes, uint32_t mbar) {
    asm volatile(
        "cp.async.bulk.shared::cluster.global.mbarrier::complete_tx::bytes "
        "[%0], [%1], %2, [%3];"
        :: "r"(dst), "l"(gsrc), "r"(bytes), "r"(mbar) : "memory");
}
// SW128 K-major desc: layout=2, version=1, SBO=64, LBO=1
__device__ __forceinline__ uint64_t sw128_desc(uint32_t addr) {
    return (2ull << 61) | (1ull << 46) | (64ull << 32) | (1ull << 16) |
           ((uint64_t)(addr >> 4) & 0x3FFFull);
}
__device__ __forceinline__ void mma_ss(uint32_t d, uint64_t ad, uint64_t bd, uint32_t en) {
    asm volatile(
        "{\n\t.reg .pred p;\n\tsetp.ne.u32 p, %4, 0;\n\t"
        "tcgen05.mma.cta_group::1.kind::f16 [%0], %1, %2, %3, {%5,%5,%5,%5}, p;\n\t}"
        :: "r"(d), "l"(ad), "l"(bd), "r"(IDESC), "r"(en), "r"(0u) : "memory");
}
__device__ __forceinline__ void mma_commit(uint32_t mbar) {
    asm volatile(
        "tcgen05.commit.cta_group::1.mbarrier::arrive::one.shared::cluster.b64 [%0];"
        :: "r"(mbar) : "memory");
}
__device__ __forceinline__ void ldtm_x32(uint32_t* r, uint32_t a) {
    asm volatile(
        "tcgen05.ld.sync.aligned.32x32b.x32.b32 "
        "{%0, %1, %2, %3, %4, %5, %6, %7, "
        " %8, %9, %10, %11, %12, %13, %14, %15, "
        " %16, %17, %18, %19, %20, %21, %22, %23, "
        " %24, %25, %26, %27, %28, %29, %30, %31}, [%32];"
        : "=r"(r[0]),  "=r"(r[1]),  "=r"(r[2]),  "=r"(r[3]),
          "=r"(r[4]),  "=r"(r[5]),  "=r"(r[6]),  "=r"(r[7]),
          "=r"(r[8]),  "=r"(r[9]),  "=r"(r[10]), "=r"(r[11]),
          "=r"(r[12]), "=r"(r[13]), "=r"(r[14]), "=r"(r[15]),
          "=r"(r[16]), "=r"(r[17]), "=r"(r[18]), "=r"(r[19]),
          "=r"(r[20]), "=r"(r[21]), "=r"(r[22]), "=r"(r[23]),
          "=r"(r[24]), "=r"(r[25]), "=r"(r[26]), "=r"(r[27]),
          "=r"(r[28]), "=r"(r[29]), "=r"(r[30]), "=r"(r[31])
        : "r"(a));
}
#endif  // HAS_TCGEN05

// =====================================================================
// Prepass: W [512,512] fp32 -> g_WP (hi/lo bf16, tile rows, pre-swizzled)
// =====================================================================
__global__ void __launch_bounds__(256) wprep_kernel(const float* __restrict__ W) {
    int item = blockIdx.x * 256 + threadIdx.x;   // 8192 items
    int f = item >> 4;
    int ch = item & 15;
    const float* wr = W + (size_t)f * 512 + ch * 32;
    float v[32];
    #pragma unroll
    for (int i = 0; i < 8; i++)
        *reinterpret_cast<float4*>(v + 4 * i) =
            *reinterpret_cast<const float4*>(wr + 4 * i);
    uint32_t hi[16], lo[16];
    #pragma unroll
    for (int p = 0; p < 16; p++) {
        uint32_t u0 = __float_as_uint(v[2 * p]), u1 = __float_as_uint(v[2 * p + 1]);
        hi[p] = __byte_perm(u0, u1, 0x7632);
        lo[p] = pack_lo_bf16x2(v[2 * p]     - __uint_as_float(u0 & 0xFFFF0000u),
                               v[2 * p + 1] - __uint_as_float(u1 & 0xFFFF0000u));
    }
    unsigned char* row = g_WP + (size_t)ch * 65536 + (size_t)f * 128;
    int r7 = f & 7;
    #pragma unroll
    for (int j = 0; j < 4; j++)
        *reinterpret_cast<uint4*>(row + ((j ^ r7) * 16)) =
            make_uint4(hi[4 * j], hi[4 * j + 1], hi[4 * j + 2], hi[4 * j + 3]);
    #pragma unroll
    for (int j = 0; j < 4; j++)
        *reinterpret_cast<uint4*>(row + (((j + 4) ^ r7) * 16)) =
            make_uint4(lo[4 * j], lo[4 * j + 1], lo[4 * j + 2], lo[4 * j + 3]);
}

// =====================================================================
// Prepass: X [512, 65536] fp32 -> g_XP (transposed, hi/lo bf16, pre-swizzled)
// Grid: 16 chunks x 128 hw-blocks (512 hw each). Smem transpose staging.
// =====================================================================
#define XP_SMEM (32 * 516 * 4)   // 66048 bytes, pad 4 floats per row
__global__ void __launch_bounds__(256) xprep_kernel(const float* __restrict__ X) {
    extern __shared__ float Xs[];
    const int tid = threadIdx.x;
    const int ch  = blockIdx.x >> 7;
    const int hwb = (blockIdx.x & 127) << 9;

    // coalesced load: [32 c x 512 hw]
    #pragma unroll
    for (int i = 0; i < 16; i++) {
        int idx = tid + 256 * i;
        int c = idx >> 7, q = idx & 127;
        float4 v = *reinterpret_cast<const float4*>(
            X + (size_t)(ch * 32 + c) * 65536 + hwb + q * 4);
        *reinterpret_cast<float4*>(&Xs[c * 516 + q * 4]) = v;
    }
    __syncthreads();

    // transposed convert + pre-swizzled store (2 hw rows per thread)
    #pragma unroll
    for (int h = 0; h < 2; h++) {
        int col = tid + 256 * h;
        int hw = hwb + col;
        int r7 = hw & 7;
        float v[32];
        #pragma unroll
        for (int c = 0; c < 32; c++) v[c] = Xs[c * 516 + col];
        uint32_t hi[16], lo[16];
        #pragma unroll
        for (int p = 0; p < 16; p++) {
            uint32_t u0 = __float_as_uint(v[2 * p]), u1 = __float_as_uint(v[2 * p + 1]);
            hi[p] = __byte_perm(u0, u1, 0x7632);
            lo[p] = pack_lo_bf16x2(v[2 * p]     - __uint_as_float(u0 & 0xFFFF0000u),
                                   v[2 * p + 1] - __uint_as_float(u1 & 0xFFFF0000u));
        }
        unsigned char* row = g_XP + (size_t)ch * 8388608 + (size_t)hw * 128;
        #pragma unroll
        for (int j = 0; j < 4; j++)
            *reinterpret_cast<uint4*>(row + ((j ^ r7) * 16)) =
                make_uint4(hi[4 * j], hi[4 * j + 1], hi[4 * j + 2], hi[4 * j + 3]);
        #pragma unroll
        for (int j = 0; j < 4; j++)
            *reinterpret_cast<uint4*>(row + (((j + 4) ^ r7) * 16)) =
                make_uint4(lo[4 * j], lo[4 * j + 1], lo[4 * j + 2], lo[4 * j + 3]);
    }
}

// =====================================================================
// Main GEMM. grid=1024: f0=(bid&1)*256, hw0=(bid>>1)*128. 2 CTAs/SM.
// =====================================================================
__global__ void __launch_bounds__(256, 2)
spconv_kernel(const float* __restrict__ X, const float* __restrict__ W,
              const float* __restrict__ bias, float* __restrict__ out)
{
    extern __shared__ char smem[];
    const int tid = threadIdx.x;
    const int f0  = (blockIdx.x & 1) * 256;
    const int hw0 = (blockIdx.x >> 1) * 128;

#if HAS_TCGEN05
    const uint32_t sb = smem_u32(smem);
    const int wid = tid >> 5;
    const int lane = tid & 31;

    if (wid == 0) {
        asm volatile("tcgen05.alloc.cta_group::1.sync.aligned.shared::cta.b32 [%0], %1;"
                     :: "r"(sb), "r"(256u) : "memory");
        asm volatile("tcgen05.relinquish_alloc_permit.cta_group::1.sync.aligned;" ::: "memory");
    }
    if (tid == 0) {
        #pragma unroll
        for (int s = 0; s < NSTAGE; s++) {
            mbar_init(sb + MBAR_FULL(s), 1);   // completed by bulk complete_tx
            mbar_init(sb + MBAR_EMPTY(s), 1);  // completed by mma commit
        }
        mbar_init(sb + MBAR_DONE, 1);
    }
    reinterpret_cast<float*>(smem + BIAS_OFF)[tid] = bias[f0 + tid];
    __syncthreads();
    uint32_t tmem;
    asm volatile("ld.shared.b32 %0, [%1];" : "=r"(tmem) : "r"(sb));

    if (tid == 0) {
        // -------- producer: bulk-copy prepacked tiles --------
        uint64_t xg, wg;
        asm("cvta.to.global.u64 %0, %1;" : "=l"(xg) : "l"((const void*)g_XP));
        asm("cvta.to.global.u64 %0, %1;" : "=l"(wg) : "l"((const void*)g_WP));
        xg += (uint64_t)hw0 * 128;
        wg += (uint64_t)f0 * 128;
        int pst = 0, pph = 1;
        for (int ch = 0; ch < NCHUNK; ch++) {
            mbar_wait(sb + MBAR_EMPTY(pst), (uint32_t)pph);
            uint32_t st = sb + STAGE0 + pst * STAGE_SZ;
            expect_tx(sb + MBAR_FULL(pst), 49152u);
            bulk_g2s(st + A_OFF, xg + (uint64_t)ch * 8388608ull, 16384u,
                     sb + MBAR_FULL(pst));
            bulk_g2s(st + B_OFF, wg + (uint64_t)ch * 65536ull, 32768u,
                     sb + MBAR_FULL(pst));
            if (++pst == NSTAGE) { pst = 0; pph ^= 1; }
        }
    } else if (tid == 32) {
        // -------- consumer: MMA issue (separate warp from producer) --------
        asm volatile("tcgen05.fence::after_thread_sync;" ::: "memory");
        int cst = 0, cph = 0;
        for (int ch = 0; ch < NCHUNK; ch++) {
            mbar_wait(sb + MBAR_FULL(cst), (uint32_t)cph);
            uint32_t base = sb + STAGE0 + cst * STAGE_SZ;
            uint64_t ad = sw128_desc(base + A_OFF);
            uint64_t bd = sw128_desc(base + B_OFF);
            #pragma unroll
            for (int k = 0; k < 2; k++) {        // two K=16 steps (hi at +0, lo at +4)
                uint64_t ah = ad + k * 2, al = ad + 4 + k * 2;
                uint64_t bh = bd + k * 2, bl = bd + 4 + k * 2;
                mma_ss(tmem, ah, bh, (ch == 0 && k == 0) ? 0u : 1u);
                mma_ss(tmem, ah, bl, 1u);
                mma_ss(tmem, al, bh, 1u);
            }
            mma_commit(sb + MBAR_EMPTY(cst));
            if (++cst == NSTAGE) { cst = 0; cph ^= 1; }
        }
        mma_commit(sb + MBAR_DONE);              // flips when ALL MMAs complete
    }

    // -------- epilogue: exact completion barrier, then TMEM -> out --------
    mbar_wait(sb + MBAR_DONE, 0u);
    asm volatile("tcgen05.fence::after_thread_sync;" ::: "memory");

    const float* bias_s = reinterpret_cast<const float*>(smem + BIAS_OFF);
    const int sub  = wid & 3;                    // TMEM subpartition
    const int half = wid >> 2;                   // f half
    const int hw   = hw0 + sub * 32 + lane;
    #pragma unroll
    for (int cb = 0; cb < 4; cb++) {
        uint32_t col = (uint32_t)(half * 128 + cb * 32);
        uint32_t r[32];
        ldtm_x32(r, tmem + col);
        asm volatile("tcgen05.wait::ld.sync.aligned;" ::: "memory");
        float* op = out + (size_t)(f0 + col) * 65536 + hw;
        #pragma unroll
        for (int j = 0; j < 32; j++) {
            float v = __uint_as_float(r[j]) + bias_s[col + j];
            op[(size_t)j * 65536] = fmaxf(v, 0.0f);
        }
    }

    __syncthreads();
    if (wid == 0) {
        asm volatile("tcgen05.dealloc.cta_group::1.sync.aligned.b32 %0, %1;"
                     :: "r"(tmem), "r"(256u));
    }

#else
    // =================== FFMA fallback (plain pass; never runs on a-pass) ===========
    float* Xs = reinterpret_cast<float*>(smem + STAGE0);           // [32][128]
    float* Ws = reinterpret_cast<float*>(smem + STAGE0 + 16384);   // [256][32]
    const int tx = tid & 15, ty = tid >> 4;
    const int hw_l = tx * 8, f_l = ty * 16;
    float acc[16][8];
    #pragma unroll
    for (int i = 0; i < 16; i++)
        #pragma unroll
        for (int j = 0; j < 8; j++) acc[i][j] = 0.0f;
    for (int ch = 0; ch < 16; ch++) {
        const int c0 = ch * 32;
        #pragma unroll
        for (int i = 0; i < 4; i++) {
            int l = tid + 256 * i, row = l >> 5, c4 = l & 31;
            *reinterpret_cast<float4*>(&Xs[row * 128 + c4 * 4]) =
                *reinterpret_cast<const float4*>(
                    &X[(size_t)(c0 + row) * 65536 + hw0 + c4 * 4]);
        }
        #pragma unroll
        for (int i = 0; i < 8; i++) {
            int l = tid + 256 * i, row = l >> 3, c4 = l & 7;
            *reinterpret_cast<float4*>(&Ws[row * 32 + c4 * 4]) =
                *reinterpret_cast<const float4*>(
                    &W[(size_t)(f0 + row) * 512 + c0 + c4 * 4]);
        }
        __syncthreads();
        #pragma unroll 4
        for (int c = 0; c < 32; c++) {
            float xv[8];
            *reinterpret_cast<float4*>(xv)     = *reinterpret_cast<float4*>(&Xs[c * 128 + hw_l]);
            *reinterpret_cast<float4*>(xv + 4) = *reinterpret_cast<float4*>(&Xs[c * 128 + hw_l + 4]);
            #pragma unroll
            for (int i = 0; i < 16; i++) {
                float wv = Ws[(f_l + i) * 32 + c];
                #pragma unroll
                for (int j = 0; j < 8; j++) acc[i][j] += wv * xv[j];
            }
        }
        __syncthreads();
    }
    #pragma unroll
    for (int i = 0; i < 16; i++) {
        float b = bias[f0 + f_l + i];
        float4 o0 = make_float4(fmaxf(acc[i][0] + b, 0.f), fmaxf(acc[i][1] + b, 0.f),
                                fmaxf(acc[i][2] + b, 0.f), fmaxf(acc[i][3] + b, 0.f));
        float4 o1 = make_float4(fmaxf(acc[i][4] + b, 0.f), fmaxf(acc[i][5] + b, 0.f),
                                fmaxf(acc[i][6] + b, 0.f), fmaxf(acc[i][7] + b, 0.f));
        float* op = out + (size_t)(f0 + f_l + i) * 65536 + hw0 + hw_l;
        *reinterpret_cast<float4*>(op)     = o0;
        *reinterpret_cast<float4*>(op + 4) = o1;
    }
#endif
}

extern "C" void kernel_launch(void* const* d_in, const int* in_sizes, int n_in,
                              void* d_out, int out_size) {
    const float* X = (const float*)d_in[0];      // [1,512,256,256]
    const float* W = (const float*)d_in[1];      // [512,512] (already masked)
    const float* bias = (const float*)d_in[n_in - 1];
    for (int i = 1; i < n_in; i++)
        if (in_sizes[i] == 512) { bias = (const float*)d_in[i]; break; }
    float* out = (float*)d_out;

    static bool attr_done = false;
    if (!attr_done) {
        cudaFuncSetAttribute(xprep_kernel,
                             cudaFuncAttributeMaxDynamicSharedMemorySize, XP_SMEM);
        cudaFuncSetAttribute(spconv_kernel,
                             cudaFuncAttributeMaxDynamicSharedMemorySize, SMEM_TOTAL);
        attr_done = true;
    }

    wprep_kernel<<<32, 256>>>(W);
    xprep_kernel<<<2048, 256, XP_SMEM>>>(X);
    spconv_kernel<<<1024, 256, SMEM_TOTAL>>>(X, W, bias, out);
}